// round 16
// baseline (speedup 1.0000x reference)
#include <cuda_runtime.h>
#include <cuda_fp16.h>
#include <cstdint>
#include <cstddef>

// BinaryLinear: y = x @ sign(W)^T + b   (32768x1024 @ 1024x1024^T)
// fp16 x + fp16 sign(W) (exact), fp32 accumulate via mma.sync m16n8k16 (HMMA).
// R12 ncu: L1/shared 91%, tensor 40.7% -> smem-bound. This round: 64x64 warp
// tiles in a 128-thread CTA (2x2 warp grid, 128x128 CTA tile) cuts ldmatrix
// duplication from (A x2 + B x4) to (A x2 + B x2): -33% smem bytes per MMA.
// x->fp16 fusion reverted (fp32 LDG path inflated L1 traffic).

static constexpr int M_TOK = 32768;
static constexpr int N_OUT = 1024;
static constexpr int K_IN  = 1024;

// CTA tile 128x128, BK=32, 4 warps (2x2), warp tile 64x64, 3 stages.
static constexpr int BM = 128, BN = 128, BK = 32;
static constexpr int PITCH  = 40;                    // halves per smem row (80B)
static constexpr int NKT    = K_IN / BK;             // 32 k-tiles
static constexpr int STAGES = 3;
static constexpr int A_HALVES = BM * PITCH;          // 5120
static constexpr int B_HALVES = BN * PITCH;          // 5120
static constexpr int STAGE_HALVES = A_HALVES + B_HALVES;       // 10240
static constexpr int SMEM_BYTES   = STAGES * STAGE_HALVES * 2; // 61440 -> 2 CTAs/SM

// Scratch: fp16 x and fp16 sign(W)
__device__ __half g_xh[(size_t)M_TOK * K_IN];   // 64 MB
__device__ __half g_ws[(size_t)N_OUT * K_IN];   // 2 MB

// ---------------------------------------------------------------------------
// Conversion kernels
// ---------------------------------------------------------------------------
__global__ void convert_x_kernel(const float* __restrict__ x) {
    size_t i = ((size_t)blockIdx.x * blockDim.x + threadIdx.x) * 4;
    float4 v = *reinterpret_cast<const float4*>(x + i);
    __half2* dst = reinterpret_cast<__half2*>(g_xh + i);
    dst[0] = __floats2half2_rn(v.x, v.y);
    dst[1] = __floats2half2_rn(v.z, v.w);
}

__global__ void convert_w_kernel(const float* __restrict__ w) {
    size_t i = ((size_t)blockIdx.x * blockDim.x + threadIdx.x) * 4;
    float4 v = *reinterpret_cast<const float4*>(w + i);
    float s0 = (float)((v.x > 0.f) - (v.x < 0.f));
    float s1 = (float)((v.y > 0.f) - (v.y < 0.f));
    float s2 = (float)((v.z > 0.f) - (v.z < 0.f));
    float s3 = (float)((v.w > 0.f) - (v.w < 0.f));
    __half2* dst = reinterpret_cast<__half2*>(g_ws + i);
    dst[0] = __floats2half2_rn(s0, s1);
    dst[1] = __floats2half2_rn(s2, s3);
}

// ---------------------------------------------------------------------------
// Helpers
// ---------------------------------------------------------------------------
__device__ __forceinline__ void cp_async16(uint32_t smem, const void* gmem) {
    asm volatile("cp.async.cg.shared.global [%0], [%1], 16;" :: "r"(smem), "l"(gmem));
}

#define MMA_16816(d, a, b)                                                    \
    asm volatile(                                                             \
        "mma.sync.aligned.m16n8k16.row.col.f32.f16.f16.f32 "                  \
        "{%0,%1,%2,%3}, {%4,%5,%6,%7}, {%8,%9}, {%0,%1,%2,%3};"               \
        : "+f"((d)[0]), "+f"((d)[1]), "+f"((d)[2]), "+f"((d)[3])              \
        : "r"((a)[0]), "r"((a)[1]), "r"((a)[2]), "r"((a)[3]),                 \
          "r"((b)[0]), "r"((b)[1]))

// ---------------------------------------------------------------------------
// GEMM: 128x128 CTA, 4 warps (2x2), warp tile 64x64, 3-stage cp.async,
// one __syncthreads per k-tile. 128 threads, 2 CTAs/SM.
// ---------------------------------------------------------------------------
__global__ __launch_bounds__(128, 2)
void gemm_kernel(const float* __restrict__ bias, float* __restrict__ out) {
    extern __shared__ __half sm[];

    const int tid    = threadIdx.x;
    const int lane   = tid & 31;
    const int warp   = tid >> 5;
    const int warp_m = warp >> 1;  // 0..1 (64-row band)
    const int warp_n = warp & 1;   // 0..1 (64-col band)
    const int bm = blockIdx.y * BM;
    const int bn = blockIdx.x * BN;

    const __half* gA = g_xh + (size_t)bm * K_IN;
    const __half* gB = g_ws + (size_t)bn * K_IN;

    // Fill: A tile = 512 16B-chunks (128 rows x 4), B same; 128 threads ->
    // 4 chunks each for A and B.
#define PREFETCH(stage)                                                                     \
    do {                                                                                    \
        __half* base = sm + ((stage) % STAGES) * STAGE_HALVES;                              \
        const int k0 = (stage) * BK;                                                        \
        _Pragma("unroll")                                                                   \
        for (int i = 0; i < 4; i++) {                                                       \
            int c = tid + i * 128;                                                          \
            int row = c >> 2, ch = (c & 3) * 8;                                             \
            cp_async16((uint32_t)__cvta_generic_to_shared(base + row * PITCH + ch),         \
                       gA + (size_t)row * K_IN + k0 + ch);                                  \
            cp_async16(                                                                     \
                (uint32_t)__cvta_generic_to_shared(base + A_HALVES + row * PITCH + ch),     \
                gB + (size_t)row * K_IN + k0 + ch);                                         \
        }                                                                                   \
    } while (0)

    float acc[4][8][4];
#pragma unroll
    for (int mi = 0; mi < 4; mi++)
#pragma unroll
        for (int ni = 0; ni < 8; ni++)
#pragma unroll
            for (int q = 0; q < 4; q++) acc[mi][ni][q] = 0.f;

    PREFETCH(0); asm volatile("cp.async.commit_group;");
    PREFETCH(1); asm volatile("cp.async.commit_group;");

    for (int kt = 0; kt < NKT; kt++) {
        asm volatile("cp.async.wait_group 1;" ::: "memory");  // stage kt landed
        __syncthreads();  // all warps done computing kt-1 -> buf (kt+2)%3 reusable

        if (kt + 2 < NKT) { PREFETCH(kt + 2); }
        asm volatile("cp.async.commit_group;");  // uniform group accounting

        const __half* sAb = sm + (kt % STAGES) * STAGE_HALVES;
        const __half* sBb = sAb + A_HALVES;

#pragma unroll
        for (int ks = 0; ks < BK; ks += 16) {
            uint32_t a[4][4];
#pragma unroll
            for (int mi = 0; mi < 4; mi++) {
                int row = warp_m * 64 + mi * 16 + (lane & 15);
                int col = ks + ((lane >> 4) << 3);
                uint32_t addr = (uint32_t)__cvta_generic_to_shared(&sAb[row * PITCH + col]);
                asm volatile(
                    "ldmatrix.sync.aligned.m8n8.x4.shared.b16 {%0,%1,%2,%3}, [%4];"
                    : "=r"(a[mi][0]), "=r"(a[mi][1]), "=r"(a[mi][2]), "=r"(a[mi][3])
                    : "r"(addr));
            }
            uint32_t b[8][2];
#pragma unroll
            for (int nj = 0; nj < 4; nj++) {
                int r = warp_n * 64 + nj * 16 + (lane & 7) + ((lane >> 4) << 3);
                int c = ks + (((lane >> 3) & 1) << 3);
                uint32_t addr = (uint32_t)__cvta_generic_to_shared(&sBb[r * PITCH + c]);
                asm volatile(
                    "ldmatrix.sync.aligned.m8n8.x4.shared.b16 {%0,%1,%2,%3}, [%4];"
                    : "=r"(b[2 * nj][0]), "=r"(b[2 * nj][1]),
                      "=r"(b[2 * nj + 1][0]), "=r"(b[2 * nj + 1][1])
                    : "r"(addr));
            }
#pragma unroll
            for (int mi = 0; mi < 4; mi++)
#pragma unroll
                for (int ni = 0; ni < 8; ni++) MMA_16816(acc[mi][ni], a[mi], b[ni]);
        }
    }

    // Epilogue: bias + fp32 store
    const int orow  = bm + warp_m * 64 + (lane >> 2);
    const int ocol0 = bn + warp_n * 64 + (lane & 3) * 2;
#pragma unroll
    for (int mi = 0; mi < 4; mi++) {
#pragma unroll
        for (int ni = 0; ni < 8; ni++) {
            int r = orow + mi * 16;
            int c = ocol0 + ni * 8;
            float b0 = bias[c];
            float b1 = bias[c + 1];
            float2 v;
            v.x = acc[mi][ni][0] + b0;
            v.y = acc[mi][ni][1] + b1;
            *reinterpret_cast<float2*>(out + (size_t)r * N_OUT + c) = v;
            v.x = acc[mi][ni][2] + b0;
            v.y = acc[mi][ni][3] + b1;
            *reinterpret_cast<float2*>(out + (size_t)(r + 8) * N_OUT + c) = v;
        }
    }
#undef PREFETCH
}

// ---------------------------------------------------------------------------
// Launch
// ---------------------------------------------------------------------------
extern "C" void kernel_launch(void* const* d_in, const int* in_sizes, int n_in,
                              void* d_out, int out_size) {
    const float* x    = (const float*)d_in[0];  // [32768, 1024]
    const float* w    = (const float*)d_in[1];  // [1024, 1024]
    const float* bias = (const float*)d_in[2];  // [1024]
    float* out = (float*)d_out;

    convert_x_kernel<<<(M_TOK * (size_t)K_IN) / (256 * 4), 256>>>(x);
    convert_w_kernel<<<((size_t)N_OUT * K_IN) / (256 * 4), 256>>>(w);

    cudaFuncSetAttribute(gemm_kernel, cudaFuncAttributeMaxDynamicSharedMemorySize, SMEM_BYTES);

    // n-tiles fastest: 8 CTAs per A-stripe co-scheduled -> A served from L2;
    // B (2 MB) stays L2-resident.
    dim3 grid(N_OUT / BN, M_TOK / BM);  // (8, 256)
    gemm_kernel<<<grid, 128, SMEM_BYTES>>>(bias, out);
}

// round 17
// speedup vs baseline: 1.0845x; 1.0845x over previous
#include <cuda_runtime.h>
#include <cuda_fp16.h>
#include <cstdint>
#include <cstddef>

// BinaryLinear: y = x @ sign(W)^T + b   (32768x1024 @ 1024x1024^T)
// fp16 x + fp16 sign(W) (exact), fp32 accumulate via mma.sync m16n8k16 (HMMA).
// R16: 64x64 warp tiles, 2 CTAs/SM -> GEMM ~209us (tensor ~57%). This round:
// whole-k-tile fragment double buffering (16 LDSM up front, 64 MMAs back-to-back)
// + 4-stage cp.async pipeline to convert latency stalls into tensor issue.

static constexpr int M_TOK = 32768;
static constexpr int N_OUT = 1024;
static constexpr int K_IN  = 1024;

// CTA tile 128x128, BK=32, 4 warps (2x2), warp tile 64x64, 4 stages.
static constexpr int BM = 128, BN = 128, BK = 32;
static constexpr int PITCH  = 40;                    // halves per smem row (80B)
static constexpr int NKT    = K_IN / BK;             // 32 k-tiles
static constexpr int STAGES = 4;
static constexpr int A_HALVES = BM * PITCH;          // 5120
static constexpr int B_HALVES = BN * PITCH;          // 5120
static constexpr int STAGE_HALVES = A_HALVES + B_HALVES;       // 10240
static constexpr int SMEM_BYTES   = STAGES * STAGE_HALVES * 2; // 81920 -> 2 CTAs/SM

// Scratch: fp16 x and fp16 sign(W)
__device__ __half g_xh[(size_t)M_TOK * K_IN];   // 64 MB
__device__ __half g_ws[(size_t)N_OUT * K_IN];   // 2 MB

// ---------------------------------------------------------------------------
// Conversion kernels
// ---------------------------------------------------------------------------
__global__ void convert_x_kernel(const float* __restrict__ x) {
    size_t i = ((size_t)blockIdx.x * blockDim.x + threadIdx.x) * 4;
    float4 v = *reinterpret_cast<const float4*>(x + i);
    __half2* dst = reinterpret_cast<__half2*>(g_xh + i);
    dst[0] = __floats2half2_rn(v.x, v.y);
    dst[1] = __floats2half2_rn(v.z, v.w);
}

__global__ void convert_w_kernel(const float* __restrict__ w) {
    size_t i = ((size_t)blockIdx.x * blockDim.x + threadIdx.x) * 4;
    float4 v = *reinterpret_cast<const float4*>(w + i);
    float s0 = (float)((v.x > 0.f) - (v.x < 0.f));
    float s1 = (float)((v.y > 0.f) - (v.y < 0.f));
    float s2 = (float)((v.z > 0.f) - (v.z < 0.f));
    float s3 = (float)((v.w > 0.f) - (v.w < 0.f));
    __half2* dst = reinterpret_cast<__half2*>(g_ws + i);
    dst[0] = __floats2half2_rn(s0, s1);
    dst[1] = __floats2half2_rn(s2, s3);
}

// ---------------------------------------------------------------------------
// Helpers
// ---------------------------------------------------------------------------
__device__ __forceinline__ void cp_async16(uint32_t smem, const void* gmem) {
    asm volatile("cp.async.cg.shared.global [%0], [%1], 16;" :: "r"(smem), "l"(gmem));
}

#define MMA_16816(d, a, b)                                                    \
    asm volatile(                                                             \
        "mma.sync.aligned.m16n8k16.row.col.f32.f16.f16.f32 "                  \
        "{%0,%1,%2,%3}, {%4,%5,%6,%7}, {%8,%9}, {%0,%1,%2,%3};"               \
        : "+f"((d)[0]), "+f"((d)[1]), "+f"((d)[2]), "+f"((d)[3])              \
        : "r"((a)[0]), "r"((a)[1]), "r"((a)[2]), "r"((a)[3]),                 \
          "r"((b)[0]), "r"((b)[1]))

#define LDSM_X4(dst, addr)                                                    \
    asm volatile(                                                             \
        "ldmatrix.sync.aligned.m8n8.x4.shared.b16 {%0,%1,%2,%3}, [%4];"       \
        : "=r"((dst)[0]), "=r"((dst)[1]), "=r"((dst)[2]), "=r"((dst)[3])      \
        : "r"(addr))

// ---------------------------------------------------------------------------
// GEMM: 128x128 CTA, 4 warps (2x2), warp tile 64x64, 4-stage cp.async,
// full-k-tile fragment preload (16 LDSM -> 64 MMA), 1 sync per k-tile.
// ---------------------------------------------------------------------------
__global__ __launch_bounds__(128, 2)
void gemm_kernel(const float* __restrict__ bias, float* __restrict__ out) {
    extern __shared__ __half sm[];

    const int tid    = threadIdx.x;
    const int lane   = tid & 31;
    const int warp   = tid >> 5;
    const int warp_m = warp >> 1;  // 0..1 (64-row band)
    const int warp_n = warp & 1;   // 0..1 (64-col band)
    const int bm = blockIdx.y * BM;
    const int bn = blockIdx.x * BN;

    const __half* gA = g_xh + (size_t)bm * K_IN;
    const __half* gB = g_ws + (size_t)bn * K_IN;

    // Fill: A tile = 512 16B-chunks (128 rows x 4), B same; 4 chunks each per thread.
#define PREFETCH(stage)                                                                     \
    do {                                                                                    \
        __half* base = sm + ((stage) % STAGES) * STAGE_HALVES;                              \
        const int k0 = (stage) * BK;                                                        \
        _Pragma("unroll")                                                                   \
        for (int i = 0; i < 4; i++) {                                                       \
            int c = tid + i * 128;                                                          \
            int row = c >> 2, ch = (c & 3) * 8;                                             \
            cp_async16((uint32_t)__cvta_generic_to_shared(base + row * PITCH + ch),         \
                       gA + (size_t)row * K_IN + k0 + ch);                                  \
            cp_async16(                                                                     \
                (uint32_t)__cvta_generic_to_shared(base + A_HALVES + row * PITCH + ch),     \
                gB + (size_t)row * K_IN + k0 + ch);                                         \
        }                                                                                   \
    } while (0)

    float acc[4][8][4];
#pragma unroll
    for (int mi = 0; mi < 4; mi++)
#pragma unroll
        for (int ni = 0; ni < 8; ni++)
#pragma unroll
            for (int q = 0; q < 4; q++) acc[mi][ni][q] = 0.f;

    // Per-warp ldmatrix source offsets (constant across tiles/ks).
    const int a_row  = warp_m * 64 + (lane & 15);
    const int a_koff = (lane >> 4) << 3;
    const int b_row  = warp_n * 64 + (lane & 7) + ((lane >> 4) << 3);
    const int b_koff = ((lane >> 3) & 1) << 3;

    PREFETCH(0); asm volatile("cp.async.commit_group;");
    PREFETCH(1); asm volatile("cp.async.commit_group;");
    PREFETCH(2); asm volatile("cp.async.commit_group;");

    for (int kt = 0; kt < NKT; kt++) {
        asm volatile("cp.async.wait_group 2;" ::: "memory");  // stage kt landed
        __syncthreads();  // all warps done computing kt-1 -> buf (kt+3)%4 reusable

        if (kt + 3 < NKT) { PREFETCH(kt + 3); }
        asm volatile("cp.async.commit_group;");  // uniform group accounting

        const __half* sAb = sm + (kt % STAGES) * STAGE_HALVES;
        const __half* sBb = sAb + A_HALVES;

        // Preload ALL fragments for both ks-steps (16 LDSM), then 64 MMAs.
        uint32_t a[2][4][4];
        uint32_t b[2][8][2];
#pragma unroll
        for (int s = 0; s < 2; s++) {
            const int ks = s * 16;
#pragma unroll
            for (int mi = 0; mi < 4; mi++) {
                uint32_t addr = (uint32_t)__cvta_generic_to_shared(
                    &sAb[(a_row + mi * 16) * PITCH + ks + a_koff]);
                LDSM_X4(a[s][mi], addr);
            }
#pragma unroll
            for (int nj = 0; nj < 4; nj++) {
                uint32_t addr = (uint32_t)__cvta_generic_to_shared(
                    &sBb[(b_row + nj * 16) * PITCH + ks + b_koff]);
                uint32_t t[4];
                LDSM_X4(t, addr);
                b[s][2 * nj][0]     = t[0];
                b[s][2 * nj][1]     = t[1];
                b[s][2 * nj + 1][0] = t[2];
                b[s][2 * nj + 1][1] = t[3];
            }
        }
#pragma unroll
        for (int s = 0; s < 2; s++)
#pragma unroll
            for (int mi = 0; mi < 4; mi++)
#pragma unroll
                for (int ni = 0; ni < 8; ni++) MMA_16816(acc[mi][ni], a[s][mi], b[s][ni]);
    }

    // Epilogue: bias + fp32 store
    const int orow  = bm + warp_m * 64 + (lane >> 2);
    const int ocol0 = bn + warp_n * 64 + (lane & 3) * 2;
#pragma unroll
    for (int mi = 0; mi < 4; mi++) {
#pragma unroll
        for (int ni = 0; ni < 8; ni++) {
            int r = orow + mi * 16;
            int c = ocol0 + ni * 8;
            float b0 = bias[c];
            float b1 = bias[c + 1];
            float2 v;
            v.x = acc[mi][ni][0] + b0;
            v.y = acc[mi][ni][1] + b1;
            *reinterpret_cast<float2*>(out + (size_t)r * N_OUT + c) = v;
            v.x = acc[mi][ni][2] + b0;
            v.y = acc[mi][ni][3] + b1;
            *reinterpret_cast<float2*>(out + (size_t)(r + 8) * N_OUT + c) = v;
        }
    }
#undef PREFETCH
}

// ---------------------------------------------------------------------------
// Launch
// ---------------------------------------------------------------------------
extern "C" void kernel_launch(void* const* d_in, const int* in_sizes, int n_in,
                              void* d_out, int out_size) {
    const float* x    = (const float*)d_in[0];  // [32768, 1024]
    const float* w    = (const float*)d_in[1];  // [1024, 1024]
    const float* bias = (const float*)d_in[2];  // [1024]
    float* out = (float*)d_out;

    convert_x_kernel<<<(M_TOK * (size_t)K_IN) / (256 * 4), 256>>>(x);
    convert_w_kernel<<<((size_t)N_OUT * K_IN) / (256 * 4), 256>>>(w);

    cudaFuncSetAttribute(gemm_kernel, cudaFuncAttributeMaxDynamicSharedMemorySize, SMEM_BYTES);

    // n-tiles fastest: 8 CTAs per A-stripe co-scheduled -> A served from L2;
    // B (2 MB) stays L2-resident.
    dim3 grid(N_OUT / BN, M_TOK / BM);  // (8, 256)
    gemm_kernel<<<grid, 128, SMEM_BYTES>>>(bias, out);
}